// round 7
// baseline (speedup 1.0000x reference)
#include <cuda_runtime.h>

#define NC 62
#define HW_BITS 18
#define HW (1 << HW_BITS)
#define NP (8 * HW)                      // 2,097,152 pixels
#define NTHREADS 256
#define NBLOCKS 2048
#define TILE_PX 128
#define NTILES (NP / TILE_PX)            // 16384
#define TILES_PER_CTA (NTILES / NBLOCKS) // 8
#define STAGES 3
#define RS 132                           // row stride (floats): 128 px + 4 pad; RS%32==4
#define TILE_FLOATS (NC * RS)            // 8184
#define TGT_OFF TILE_FLOATS              // targets after the tile (16B aligned)
#define STAGE_FLOATS (TILE_FLOATS + TILE_PX)   // 8312
#define SMEM_BYTES (STAGES * STAGE_FLOATS * 4) // 99744 -> 2 CTAs/SM
#define IGN 255
#define SMOOTH 1e-6f
#define PAD 32
#define OWNER_MASK 0x0F0F0F0Fu           // lanes with (lane&7) < 4

__device__ float g_acc[NC * PAD];
__device__ float g_inter[NC * PAD];
__device__ float g_tgt[NC * PAD];
__device__ unsigned int g_count;

// Stage fill: 62 rows x 32 16B-chunks (pred) + 32 chunks (target) = 2016 cp.async
__device__ __forceinline__ void fill_stage(float* sm, const float* pred,
                                           const int* target, int tile, int tid) {
    int n = tile >> (HW_BITS - 7);                       // tile / 2048
    size_t hw0 = (size_t)(tile & ((1 << (HW_BITS - 7)) - 1)) << 7;
    unsigned sbase = (unsigned)__cvta_generic_to_shared(sm);
#pragma unroll
    for (int k = 0; k < 8; k++) {
        int idx = tid + k * NTHREADS;                    // 0..2047
        if (idx < NC * 32) {
            int c = idx >> 5, ch = idx & 31;
            const float* src =
                pred + (((size_t)(n * NC + c)) << HW_BITS) + hw0 + ch * 4;
            unsigned dst = sbase + (unsigned)((c * RS + ch * 4) * 4);
            asm volatile("cp.async.cg.shared.global [%0], [%1], 16;"
                         :: "r"(dst), "l"(src));
        } else if (idx < NC * 32 + 32) {
            int ch = idx - NC * 32;
            const int* src = target + (size_t)tile * TILE_PX + ch * 4;
            unsigned dst = sbase + (unsigned)((TGT_OFF + ch * 4) * 4);
            asm volatile("cp.async.cg.shared.global [%0], [%1], 16;"
                         :: "r"(dst), "l"(src));
        }
    }
}

__global__ __launch_bounds__(NTHREADS, 2) void dice_kernel(
    const float* __restrict__ pred, const int* __restrict__ target,
    float* __restrict__ out) {
    extern __shared__ float smem[];
    __shared__ float s_acc[NC];
    __shared__ float s_inter[NC];
    __shared__ float s_tgt[NC];
    __shared__ bool s_last;

    int tid = threadIdx.x;
    int lane = tid & 31;
    int w = tid >> 5;        // warp 0..7, owns pixels [w*16, w*16+16) of each tile
    int h = lane & 7;        // channel chunk: c = j*8 + h
    int q = lane >> 3;       // pixel quad 0..3

    if (tid < NC) {
        s_acc[tid] = 0.0f;
        s_inter[tid] = 0.0f;
        s_tgt[tid] = 0.0f;
    }

    // Prologue: prefetch stages 0..2
#pragma unroll
    for (int s = 0; s < STAGES; s++) {
        fill_stage(smem + s * STAGE_FLOATS, pred, target,
                   blockIdx.x + s * NBLOCKS, tid);
        asm volatile("cp.async.commit_group;");
    }

    float acc[8];
#pragma unroll
    for (int j = 0; j < 8; j++) acc[j] = 0.0f;

#pragma unroll 1
    for (int i = 0; i < TILES_PER_CTA; i++) {
        asm volatile("cp.async.wait_group 2;");
        __syncthreads();   // stage (i%3) fully resident for all threads

        float* st = smem + (i % STAGES) * STAGE_FLOATS;
        const int* tg = (const int*)(st + TGT_OFF);

        int pxb = w * 16 + q * 4;  // this lane's quad base within the tile
        int4 t4 = *(const int4*)(tg + pxb);

        // Phase A: 8 LDS.128 per lane. RS%32==4 and c=8j+h make every
        // 8-lane quarter hit 8 distinct banks -> conflict-free.
        float4 v[8];
#pragma unroll
        for (int j = 0; j < 8; j++) {
            int c = j * 8 + h;
            v[j] = (c < NC) ? *(const float4*)(st + c * RS + pxb)
                            : make_float4(0.f, 0.f, 0.f, 0.f);
        }

        // Phase B: exp in place + per-pixel partial Z
        float zx = 0.f, zy = 0.f, zz = 0.f, zw = 0.f;
#pragma unroll
        for (int j = 0; j < 8; j++) {
            bool cv = (j * 8 + h < NC);
            float ex = cv ? __expf(v[j].x) : 0.f;
            float ey = cv ? __expf(v[j].y) : 0.f;
            float ez = cv ? __expf(v[j].z) : 0.f;
            float ew = cv ? __expf(v[j].w) : 0.f;
            v[j].x = ex; v[j].y = ey; v[j].z = ez; v[j].w = ew;
            zx += ex; zy += ey; zz += ez; zw += ew;
        }
        // combine Z across the 8 h-lanes of this quad
        zx += __shfl_xor_sync(0xffffffffu, zx, 1);
        zx += __shfl_xor_sync(0xffffffffu, zx, 2);
        zx += __shfl_xor_sync(0xffffffffu, zx, 4);
        zy += __shfl_xor_sync(0xffffffffu, zy, 1);
        zy += __shfl_xor_sync(0xffffffffu, zy, 2);
        zy += __shfl_xor_sync(0xffffffffu, zy, 4);
        zz += __shfl_xor_sync(0xffffffffu, zz, 1);
        zz += __shfl_xor_sync(0xffffffffu, zz, 2);
        zz += __shfl_xor_sync(0xffffffffu, zz, 4);
        zw += __shfl_xor_sync(0xffffffffu, zw, 1);
        zw += __shfl_xor_sync(0xffffffffu, zw, 2);
        zw += __shfl_xor_sync(0xffffffffu, zw, 4);

        float sx = (t4.x != IGN) ? __fdividef(1.f, zx) : 0.f;  // invZ * validf
        float sy = (t4.y != IGN) ? __fdividef(1.f, zy) : 0.f;
        float sz = (t4.z != IGN) ? __fdividef(1.f, zz) : 0.f;
        float sw = (t4.w != IGN) ? __fdividef(1.f, zw) : 0.f;

        // Phase C: per-class register accumulation
#pragma unroll
        for (int j = 0; j < 8; j++) {
            acc[j] = fmaf(v[j].x, sx,
                     fmaf(v[j].y, sy,
                     fmaf(v[j].z, sz,
                     fmaf(v[j].w, sw, acc[j]))));
        }

        // Phase D: lanes with h<4 own pixel pxb+h. Gather softmax[target]
        // straight from smem (logits untouched) + shared atomics.
        if (h < 4) {
            int tmine = (h == 0) ? t4.x : (h == 1) ? t4.y : (h == 2) ? t4.z : t4.w;
            float smine = (h == 0) ? sx : (h == 1) ? sy : (h == 2) ? sz : sw;
            bool valid = (tmine != IGN);
            int tc = valid ? tmine : 0;
            float xt = st[tc * RS + pxb + h];
            atomicAdd(&s_inter[tc], __expf(xt) * smine);  // 0 if invalid

            unsigned m = __match_any_sync(OWNER_MASK, tc);
            unsigned vb = __ballot_sync(OWNER_MASK, valid);
            if (lane == (int)(__ffs(m) - 1)) {
                int cnt = __popc(m & vb);
                if (cnt) atomicAdd(&s_tgt[tc], (float)cnt);
            }
        }

        __syncthreads();   // all warps done with stage before refill
        if (i + STAGES < TILES_PER_CTA)
            fill_stage(smem + (i % STAGES) * STAGE_FLOATS, pred, target,
                       blockIdx.x + (i + STAGES) * NBLOCKS, tid);
        asm volatile("cp.async.commit_group;");  // (possibly empty) keeps count uniform
    }

    // Reduce acc across the 4 q-lanes sharing chunk h, then to shared
#pragma unroll
    for (int j = 0; j < 8; j++) {
        float va = acc[j];
        va += __shfl_xor_sync(0xffffffffu, va, 8);
        va += __shfl_xor_sync(0xffffffffu, va, 16);
        if (lane < 8) {
            int c = j * 8 + lane;
            if (c < NC) atomicAdd(&s_acc[c], va);
        }
    }
    __syncthreads();

    // One global atomic per class per block (padded -> spread L2 slices)
    if (tid < NC) {
        atomicAdd(&g_acc[tid * PAD], s_acc[tid]);
        atomicAdd(&g_inter[tid * PAD], s_inter[tid]);
        atomicAdd(&g_tgt[tid * PAD], s_tgt[tid]);
    }
    __threadfence();
    __syncthreads();
    if (tid == 0) {
        unsigned prev = atomicAdd(&g_count, 1u);
        s_last = (prev == NBLOCKS - 1);
    }
    __syncthreads();
    if (!s_last) return;

    // ---- last block: finalize ----
    float dice = 0.0f, has = 0.0f;
    if (tid < NC) {
        float ps = atomicAdd(&g_acc[tid * PAD], 0.0f);
        float iv = atomicAdd(&g_inter[tid * PAD], 0.0f);
        float tg = atomicAdd(&g_tgt[tid * PAD], 0.0f);
        float un = ps + tg;
        if (un > 0.0f) {
            has = 1.0f;
            dice = (2.0f * iv + SMOOTH) / (un + SMOOTH);
        }
    }
    __shared__ float sd[8], sh[8];
#pragma unroll
    for (int o = 16; o > 0; o >>= 1) {
        dice += __shfl_xor_sync(0xffffffffu, dice, o);
        has += __shfl_xor_sync(0xffffffffu, has, o);
    }
    if (lane == 0) {
        sd[tid >> 5] = dice;
        sh[tid >> 5] = has;
    }
    __syncthreads();
    if (tid == 0) {
        float ds = 0.0f, hs = 0.0f;
#pragma unroll
        for (int ww = 0; ww < NTHREADS / 32; ww++) {
            ds += sd[ww];
            hs += sh[ww];
        }
        float mean = (hs > 0.0f) ? (ds / fmaxf(hs, 1.0f)) : 1.0f;
        out[0] = 1.0f - mean;
    }
    __syncthreads();
    // reset globals so every graph replay starts clean
    if (tid < NC) {
        g_acc[tid * PAD] = 0.0f;
        g_inter[tid * PAD] = 0.0f;
        g_tgt[tid * PAD] = 0.0f;
    }
    if (tid == 0) g_count = 0;
}

extern "C" void kernel_launch(void* const* d_in, const int* in_sizes, int n_in,
                              void* d_out, int out_size) {
    const float* pred = (const float*)d_in[0];
    const int* target = (const int*)d_in[1];
    float* out = (float*)d_out;
    cudaFuncSetAttribute(dice_kernel, cudaFuncAttributeMaxDynamicSharedMemorySize,
                         SMEM_BYTES);
    dice_kernel<<<NBLOCKS, NTHREADS, SMEM_BYTES>>>(pred, target, out);
}

// round 8
// speedup vs baseline: 1.2270x; 1.2270x over previous
#include <cuda_runtime.h>

#define NC 62
#define HW_BITS 18
#define HW (1 << HW_BITS)
#define NP (8 * HW)                      // 2,097,152 pixels
#define NTHREADS 256
#define NBLOCKS 2048
#define TILE_PX 128
#define NTILES (NP / TILE_PX)            // 16384
#define TILES_PER_CTA (NTILES / NBLOCKS) // 8
#define STAGES 2
#define RS 132                           // row stride (floats): 128 px + 4 pad; RS%32==4
#define TILE_FLOATS (NC * RS)            // 8184
#define TGT_OFF TILE_FLOATS              // targets after the tile (16B aligned)
#define STAGE_FLOATS (TILE_FLOATS + TILE_PX)   // 8312
#define SMEM_BYTES (STAGES * STAGE_FLOATS * 4) // 66496 -> 3 CTAs/SM
#define IGN 255
#define SMOOTH 1e-6f
#define PAD 32
#define OWNER_MASK 0x0F0F0F0Fu           // lanes with (lane&7) < 4

__device__ float g_acc[NC * PAD];
__device__ float g_inter[NC * PAD];
__device__ float g_tgt[NC * PAD];
__device__ unsigned int g_count;

// Stage fill: 62 rows x 32 16B-chunks (pred) + 32 chunks (target) = 2016 cp.async
__device__ __forceinline__ void fill_stage(float* sm, const float* pred,
                                           const int* target, int tile, int tid) {
    int n = tile >> (HW_BITS - 7);                       // tile / 2048
    size_t hw0 = (size_t)(tile & ((1 << (HW_BITS - 7)) - 1)) << 7;
    unsigned sbase = (unsigned)__cvta_generic_to_shared(sm);
#pragma unroll
    for (int k = 0; k < 8; k++) {
        int idx = tid + k * NTHREADS;                    // 0..2047
        if (idx < NC * 32) {
            int c = idx >> 5, ch = idx & 31;
            const float* src =
                pred + (((size_t)(n * NC + c)) << HW_BITS) + hw0 + ch * 4;
            unsigned dst = sbase + (unsigned)((c * RS + ch * 4) * 4);
            asm volatile("cp.async.cg.shared.global [%0], [%1], 16;"
                         :: "r"(dst), "l"(src));
        } else if (idx < NC * 32 + 32) {
            int ch = idx - NC * 32;
            const int* src = target + (size_t)tile * TILE_PX + ch * 4;
            unsigned dst = sbase + (unsigned)((TGT_OFF + ch * 4) * 4);
            asm volatile("cp.async.cg.shared.global [%0], [%1], 16;"
                         :: "r"(dst), "l"(src));
        }
    }
}

__global__ __launch_bounds__(NTHREADS, 3) void dice_kernel(
    const float* __restrict__ pred, const int* __restrict__ target,
    float* __restrict__ out) {
    extern __shared__ float smem[];
    __shared__ float s_acc[NC];
    __shared__ float s_inter[NC];
    __shared__ float s_tgt[NC];
    __shared__ bool s_last;

    int tid = threadIdx.x;
    int lane = tid & 31;
    int w = tid >> 5;        // warp 0..7, owns pixels [w*16, w*16+16) of each tile
    int h = lane & 7;        // channel chunk: c = j*8 + h
    int q = lane >> 3;       // pixel quad 0..3

    if (tid < NC) {
        s_acc[tid] = 0.0f;
        s_inter[tid] = 0.0f;
        s_tgt[tid] = 0.0f;
    }

    // Prologue: prefetch stages 0..1
#pragma unroll
    for (int s = 0; s < STAGES; s++) {
        fill_stage(smem + s * STAGE_FLOATS, pred, target,
                   blockIdx.x + s * NBLOCKS, tid);
        asm volatile("cp.async.commit_group;");
    }

    float acc[8];
#pragma unroll
    for (int j = 0; j < 8; j++) acc[j] = 0.0f;

#pragma unroll 1
    for (int i = 0; i < TILES_PER_CTA; i++) {
        asm volatile("cp.async.wait_group 1;");
        __syncthreads();   // stage (i%2) fully resident for all threads

        float* st = smem + (i % STAGES) * STAGE_FLOATS;
        const int* tg = (const int*)(st + TGT_OFF);

        int pxb = w * 16 + q * 4;  // this lane's quad base within the tile
        int4 t4 = *(const int4*)(tg + pxb);

        // Phase A: 8 LDS.128 per lane. RS%32==4 and c=8j+h make every
        // 8-lane quarter hit 8 distinct 16B banks -> conflict-free.
        float4 v[8];
#pragma unroll
        for (int j = 0; j < 8; j++) {
            int c = j * 8 + h;
            v[j] = (c < NC) ? *(const float4*)(st + c * RS + pxb)
                            : make_float4(0.f, 0.f, 0.f, 0.f);
        }

        // Phase B: exp in place + per-pixel partial Z
        float zx = 0.f, zy = 0.f, zz = 0.f, zw = 0.f;
#pragma unroll
        for (int j = 0; j < 8; j++) {
            bool cv = (j * 8 + h < NC);
            float ex = cv ? __expf(v[j].x) : 0.f;
            float ey = cv ? __expf(v[j].y) : 0.f;
            float ez = cv ? __expf(v[j].z) : 0.f;
            float ew = cv ? __expf(v[j].w) : 0.f;
            v[j].x = ex; v[j].y = ey; v[j].z = ez; v[j].w = ew;
            zx += ex; zy += ey; zz += ez; zw += ew;
        }
        // combine Z across the 8 h-lanes of this quad (4 independent chains)
        zx += __shfl_xor_sync(0xffffffffu, zx, 1);
        zy += __shfl_xor_sync(0xffffffffu, zy, 1);
        zz += __shfl_xor_sync(0xffffffffu, zz, 1);
        zw += __shfl_xor_sync(0xffffffffu, zw, 1);
        zx += __shfl_xor_sync(0xffffffffu, zx, 2);
        zy += __shfl_xor_sync(0xffffffffu, zy, 2);
        zz += __shfl_xor_sync(0xffffffffu, zz, 2);
        zw += __shfl_xor_sync(0xffffffffu, zw, 2);
        zx += __shfl_xor_sync(0xffffffffu, zx, 4);
        zy += __shfl_xor_sync(0xffffffffu, zy, 4);
        zz += __shfl_xor_sync(0xffffffffu, zz, 4);
        zw += __shfl_xor_sync(0xffffffffu, zw, 4);

        float sx = (t4.x != IGN) ? __fdividef(1.f, zx) : 0.f;  // invZ * validf
        float sy = (t4.y != IGN) ? __fdividef(1.f, zy) : 0.f;
        float sz = (t4.z != IGN) ? __fdividef(1.f, zz) : 0.f;
        float sw = (t4.w != IGN) ? __fdividef(1.f, zw) : 0.f;

        // Phase C: per-class register accumulation
#pragma unroll
        for (int j = 0; j < 8; j++) {
            acc[j] = fmaf(v[j].x, sx,
                     fmaf(v[j].y, sy,
                     fmaf(v[j].z, sz,
                     fmaf(v[j].w, sw, acc[j]))));
        }

        // Phase D: lanes with h<4 own pixel pxb+h. Gather softmax[target]
        // straight from smem + shared atomics.
        if (h < 4) {
            int tmine = (h == 0) ? t4.x : (h == 1) ? t4.y : (h == 2) ? t4.z : t4.w;
            float smine = (h == 0) ? sx : (h == 1) ? sy : (h == 2) ? sz : sw;
            bool valid = (tmine != IGN);
            int tc = valid ? tmine : 0;
            float xt = st[tc * RS + pxb + h];
            atomicAdd(&s_inter[tc], __expf(xt) * smine);  // 0 if invalid

            unsigned m = __match_any_sync(OWNER_MASK, tc);
            unsigned vb = __ballot_sync(OWNER_MASK, valid);
            if (lane == (int)(__ffs(m) - 1)) {
                int cnt = __popc(m & vb);
                if (cnt) atomicAdd(&s_tgt[tc], (float)cnt);
            }
        }

        __syncthreads();   // all warps done with stage before refill
        if (i + STAGES < TILES_PER_CTA)
            fill_stage(smem + (i % STAGES) * STAGE_FLOATS, pred, target,
                       blockIdx.x + (i + STAGES) * NBLOCKS, tid);
        asm volatile("cp.async.commit_group;");  // (possibly empty) keeps count uniform
    }

    // Reduce acc across the 4 q-lanes sharing chunk h, then to shared
#pragma unroll
    for (int j = 0; j < 8; j++) {
        float va = acc[j];
        va += __shfl_xor_sync(0xffffffffu, va, 8);
        va += __shfl_xor_sync(0xffffffffu, va, 16);
        if (lane < 8) {
            int c = j * 8 + lane;
            if (c < NC) atomicAdd(&s_acc[c], va);
        }
    }
    __syncthreads();

    // One global atomic per class per block (padded -> spread L2 slices)
    if (tid < NC) {
        atomicAdd(&g_acc[tid * PAD], s_acc[tid]);
        atomicAdd(&g_inter[tid * PAD], s_inter[tid]);
        atomicAdd(&g_tgt[tid * PAD], s_tgt[tid]);
    }
    __threadfence();
    __syncthreads();
    if (tid == 0) {
        unsigned prev = atomicAdd(&g_count, 1u);
        s_last = (prev == NBLOCKS - 1);
    }
    __syncthreads();
    if (!s_last) return;

    // ---- last block: finalize ----
    float dice = 0.0f, has = 0.0f;
    if (tid < NC) {
        float ps = atomicAdd(&g_acc[tid * PAD], 0.0f);
        float iv = atomicAdd(&g_inter[tid * PAD], 0.0f);
        float tg = atomicAdd(&g_tgt[tid * PAD], 0.0f);
        float un = ps + tg;
        if (un > 0.0f) {
            has = 1.0f;
            dice = (2.0f * iv + SMOOTH) / (un + SMOOTH);
        }
    }
    __shared__ float sd[8], sh[8];
#pragma unroll
    for (int o = 16; o > 0; o >>= 1) {
        dice += __shfl_xor_sync(0xffffffffu, dice, o);
        has += __shfl_xor_sync(0xffffffffu, has, o);
    }
    if (lane == 0) {
        sd[tid >> 5] = dice;
        sh[tid >> 5] = has;
    }
    __syncthreads();
    if (tid == 0) {
        float ds = 0.0f, hs = 0.0f;
#pragma unroll
        for (int ww = 0; ww < NTHREADS / 32; ww++) {
            ds += sd[ww];
            hs += sh[ww];
        }
        float mean = (hs > 0.0f) ? (ds / fmaxf(hs, 1.0f)) : 1.0f;
        out[0] = 1.0f - mean;
    }
    __syncthreads();
    // reset globals so every graph replay starts clean
    if (tid < NC) {
        g_acc[tid * PAD] = 0.0f;
        g_inter[tid * PAD] = 0.0f;
        g_tgt[tid * PAD] = 0.0f;
    }
    if (tid == 0) g_count = 0;
}

extern "C" void kernel_launch(void* const* d_in, const int* in_sizes, int n_in,
                              void* d_out, int out_size) {
    const float* pred = (const float*)d_in[0];
    const int* target = (const int*)d_in[1];
    float* out = (float*)d_out;
    cudaFuncSetAttribute(dice_kernel, cudaFuncAttributeMaxDynamicSharedMemorySize,
                         SMEM_BYTES);
    dice_kernel<<<NBLOCKS, NTHREADS, SMEM_BYTES>>>(pred, target, out);
}

// round 9
// speedup vs baseline: 1.2308x; 1.0031x over previous
#include <cuda_runtime.h>

#define NC 62
#define HW_BITS 18
#define HW (1 << HW_BITS)
#define NP (8 * HW)                      // 2,097,152 pixels
#define NTHREADS 256
#define NBLOCKS 2048
#define TILE_PX 128
#define NTILES (NP / TILE_PX)            // 16384
#define TILES_PER_CTA (NTILES / NBLOCKS) // 8
#define STAGES 2
#define RS 132                           // row stride (floats): 128 px + 4 pad; RS%32==4
#define TILE_FLOATS (NC * RS)            // 8184
#define TGT_OFF TILE_FLOATS              // targets after the tile (16B aligned)
#define STAGE_FLOATS (TILE_FLOATS + TILE_PX)   // 8312
#define SMEM_BYTES (STAGES * STAGE_FLOATS * 4) // 66496 -> 3 CTAs/SM
#define IGN 255
#define SMOOTH 1e-6f
#define PAD 32
#define OWNER_MASK 0x0F0F0F0Fu           // lanes with (lane&7) < 4

__device__ float g_acc[NC * PAD];
__device__ float g_inter[NC * PAD];
__device__ float g_tgt[NC * PAD];
__device__ unsigned int g_count;

// Stage fill: 62 rows x 32 16B-chunks (pred) + 32 chunks (target) = 2016 cp.async
__device__ __forceinline__ void fill_stage(float* sm, const float* pred,
                                           const int* target, int tile, int tid) {
    int n = tile >> (HW_BITS - 7);                       // tile / 2048
    size_t hw0 = (size_t)(tile & ((1 << (HW_BITS - 7)) - 1)) << 7;
    unsigned sbase = (unsigned)__cvta_generic_to_shared(sm);
#pragma unroll
    for (int k = 0; k < 8; k++) {
        int idx = tid + k * NTHREADS;                    // 0..2047
        if (idx < NC * 32) {
            int c = idx >> 5, ch = idx & 31;
            const float* src =
                pred + (((size_t)(n * NC + c)) << HW_BITS) + hw0 + ch * 4;
            unsigned dst = sbase + (unsigned)((c * RS + ch * 4) * 4);
            asm volatile("cp.async.cg.shared.global [%0], [%1], 16;"
                         :: "r"(dst), "l"(src));
        } else if (idx < NC * 32 + 32) {
            int ch = idx - NC * 32;
            const int* src = target + (size_t)tile * TILE_PX + ch * 4;
            unsigned dst = sbase + (unsigned)((TGT_OFF + ch * 4) * 4);
            asm volatile("cp.async.cg.shared.global [%0], [%1], 16;"
                         :: "r"(dst), "l"(src));
        }
    }
}

__global__ __launch_bounds__(NTHREADS, 3) void dice_kernel(
    const float* __restrict__ pred, const int* __restrict__ target,
    float* __restrict__ out) {
    extern __shared__ float smem[];
    __shared__ float s_acc[NC];
    __shared__ float s_inter[NC];
    __shared__ float s_tgt[NC];
    __shared__ bool s_last;

    int tid = threadIdx.x;
    int lane = tid & 31;
    int w = tid >> 5;        // warp 0..7, owns pixels [w*16, w*16+16) of each tile
    int h = lane & 7;        // channel chunk: c = j*8 + h
    int q = lane >> 3;       // pixel quad 0..3

    if (tid < NC) {
        s_acc[tid] = 0.0f;
        s_inter[tid] = 0.0f;
        s_tgt[tid] = 0.0f;
    }

    // Prologue: prefetch stages 0..1
#pragma unroll
    for (int s = 0; s < STAGES; s++) {
        fill_stage(smem + s * STAGE_FLOATS, pred, target,
                   blockIdx.x + s * NBLOCKS, tid);
        asm volatile("cp.async.commit_group;");
    }

    float acc[8];
#pragma unroll
    for (int j = 0; j < 8; j++) acc[j] = 0.0f;

#pragma unroll 1
    for (int i = 0; i < TILES_PER_CTA; i++) {
        asm volatile("cp.async.wait_group 1;");
        __syncthreads();   // stage (i%2) fully resident for all threads

        float* st = smem + (i % STAGES) * STAGE_FLOATS;
        const int* tg = (const int*)(st + TGT_OFF);

        int pxb = w * 16 + q * 4;  // this lane's quad base within the tile
        int4 t4 = *(const int4*)(tg + pxb);

        // Phase A: 8 LDS.128 per lane. RS%32==4 and c=8j+h make every
        // 8-lane quarter hit 8 distinct 16B banks -> conflict-free.
        float4 v[8];
#pragma unroll
        for (int j = 0; j < 8; j++) {
            int c = j * 8 + h;
            v[j] = (c < NC) ? *(const float4*)(st + c * RS + pxb)
                            : make_float4(0.f, 0.f, 0.f, 0.f);
        }

        // Phase B: exp in place + per-pixel partial Z
        float zx = 0.f, zy = 0.f, zz = 0.f, zw = 0.f;
#pragma unroll
        for (int j = 0; j < 8; j++) {
            bool cv = (j * 8 + h < NC);
            float ex = cv ? __expf(v[j].x) : 0.f;
            float ey = cv ? __expf(v[j].y) : 0.f;
            float ez = cv ? __expf(v[j].z) : 0.f;
            float ew = cv ? __expf(v[j].w) : 0.f;
            v[j].x = ex; v[j].y = ey; v[j].z = ez; v[j].w = ew;
            zx += ex; zy += ey; zz += ez; zw += ew;
        }
        // combine Z across the 8 h-lanes of this quad (4 independent chains)
        zx += __shfl_xor_sync(0xffffffffu, zx, 1);
        zy += __shfl_xor_sync(0xffffffffu, zy, 1);
        zz += __shfl_xor_sync(0xffffffffu, zz, 1);
        zw += __shfl_xor_sync(0xffffffffu, zw, 1);
        zx += __shfl_xor_sync(0xffffffffu, zx, 2);
        zy += __shfl_xor_sync(0xffffffffu, zy, 2);
        zz += __shfl_xor_sync(0xffffffffu, zz, 2);
        zw += __shfl_xor_sync(0xffffffffu, zw, 2);
        zx += __shfl_xor_sync(0xffffffffu, zx, 4);
        zy += __shfl_xor_sync(0xffffffffu, zy, 4);
        zz += __shfl_xor_sync(0xffffffffu, zz, 4);
        zw += __shfl_xor_sync(0xffffffffu, zw, 4);

        float sx = (t4.x != IGN) ? __fdividef(1.f, zx) : 0.f;  // invZ * validf
        float sy = (t4.y != IGN) ? __fdividef(1.f, zy) : 0.f;
        float sz = (t4.z != IGN) ? __fdividef(1.f, zz) : 0.f;
        float sw = (t4.w != IGN) ? __fdividef(1.f, zw) : 0.f;

        // Phase C: per-class register accumulation
#pragma unroll
        for (int j = 0; j < 8; j++) {
            acc[j] = fmaf(v[j].x, sx,
                     fmaf(v[j].y, sy,
                     fmaf(v[j].z, sz,
                     fmaf(v[j].w, sw, acc[j]))));
        }

        // Phase D: lanes with h<4 own pixel pxb+h. Gather softmax[target]
        // straight from smem + shared atomics.
        if (h < 4) {
            int tmine = (h == 0) ? t4.x : (h == 1) ? t4.y : (h == 2) ? t4.z : t4.w;
            float smine = (h == 0) ? sx : (h == 1) ? sy : (h == 2) ? sz : sw;
            bool valid = (tmine != IGN);
            int tc = valid ? tmine : 0;
            float xt = st[tc * RS + pxb + h];
            atomicAdd(&s_inter[tc], __expf(xt) * smine);  // 0 if invalid

            unsigned m = __match_any_sync(OWNER_MASK, tc);
            unsigned vb = __ballot_sync(OWNER_MASK, valid);
            if (lane == (int)(__ffs(m) - 1)) {
                int cnt = __popc(m & vb);
                if (cnt) atomicAdd(&s_tgt[tc], (float)cnt);
            }
        }

        __syncthreads();   // all warps done with stage before refill
        if (i + STAGES < TILES_PER_CTA)
            fill_stage(smem + (i % STAGES) * STAGE_FLOATS, pred, target,
                       blockIdx.x + (i + STAGES) * NBLOCKS, tid);
        asm volatile("cp.async.commit_group;");  // (possibly empty) keeps count uniform
    }

    // Reduce acc across the 4 q-lanes sharing chunk h, then to shared
#pragma unroll
    for (int j = 0; j < 8; j++) {
        float va = acc[j];
        va += __shfl_xor_sync(0xffffffffu, va, 8);
        va += __shfl_xor_sync(0xffffffffu, va, 16);
        if (lane < 8) {
            int c = j * 8 + lane;
            if (c < NC) atomicAdd(&s_acc[c], va);
        }
    }
    __syncthreads();

    // One global atomic per class per block (padded -> spread L2 slices)
    if (tid < NC) {
        atomicAdd(&g_acc[tid * PAD], s_acc[tid]);
        atomicAdd(&g_inter[tid * PAD], s_inter[tid]);
        atomicAdd(&g_tgt[tid * PAD], s_tgt[tid]);
    }
    __threadfence();
    __syncthreads();
    if (tid == 0) {
        unsigned prev = atomicAdd(&g_count, 1u);
        s_last = (prev == NBLOCKS - 1);
    }
    __syncthreads();
    if (!s_last) return;

    // ---- last block: finalize ----
    float dice = 0.0f, has = 0.0f;
    if (tid < NC) {
        float ps = atomicAdd(&g_acc[tid * PAD], 0.0f);
        float iv = atomicAdd(&g_inter[tid * PAD], 0.0f);
        float tg = atomicAdd(&g_tgt[tid * PAD], 0.0f);
        float un = ps + tg;
        if (un > 0.0f) {
            has = 1.0f;
            dice = (2.0f * iv + SMOOTH) / (un + SMOOTH);
        }
    }
    __shared__ float sd[8], sh[8];
#pragma unroll
    for (int o = 16; o > 0; o >>= 1) {
        dice += __shfl_xor_sync(0xffffffffu, dice, o);
        has += __shfl_xor_sync(0xffffffffu, has, o);
    }
    if (lane == 0) {
        sd[tid >> 5] = dice;
        sh[tid >> 5] = has;
    }
    __syncthreads();
    if (tid == 0) {
        float ds = 0.0f, hs = 0.0f;
#pragma unroll
        for (int ww = 0; ww < NTHREADS / 32; ww++) {
            ds += sd[ww];
            hs += sh[ww];
        }
        float mean = (hs > 0.0f) ? (ds / fmaxf(hs, 1.0f)) : 1.0f;
        out[0] = 1.0f - mean;
    }
    __syncthreads();
    // reset globals so every graph replay starts clean
    if (tid < NC) {
        g_acc[tid * PAD] = 0.0f;
        g_inter[tid * PAD] = 0.0f;
        g_tgt[tid * PAD] = 0.0f;
    }
    if (tid == 0) g_count = 0;
}

extern "C" void kernel_launch(void* const* d_in, const int* in_sizes, int n_in,
                              void* d_out, int out_size) {
    const float* pred = (const float*)d_in[0];
    const int* target = (const int*)d_in[1];
    float* out = (float*)d_out;
    cudaFuncSetAttribute(dice_kernel, cudaFuncAttributeMaxDynamicSharedMemorySize,
                         SMEM_BYTES);
    dice_kernel<<<NBLOCKS, NTHREADS, SMEM_BYTES>>>(pred, target, out);
}